// round 9
// baseline (speedup 1.0000x reference)
#include <cuda_runtime.h>
#include <cuda_bf16.h>
#include <math.h>

#define T_LEN    8192
#define VOCAB    50257
#define NCHUNK   37               // 16 qblocks x 37 chunks = 592 CTAs = exactly 4/SM
#define NQBLK    16
#define QBLK     512              // queries per CTA
#define NTHREADS 128
#define QPT      4
#define KMAX     222              // ceil(8192/37)

// scratch (device globals; no allocation allowed)
__device__ float4 g_qp[T_LEN];                // q' = QSCALE * (Wk^T Wq) p
__device__ float4 g_p[T_LEN];                 // p with w=1.0f
__device__ float4 g_part[NCHUNK * T_LEN];     // per-chunk partial (sum e*p, sum e)
__device__ unsigned g_cnt[NQBLK];             // monotonic arrival counters (mod-37 logic)

__device__ __forceinline__ float ex2f(float x) {
    float r; asm("ex2.approx.f32 %0, %1;" : "=f"(r) : "f"(x)); return r;
}

// ---------------------------------------------------------------------------
// Kernel 1: gather + posenc; emit p and q' = QSCALE*(Wk^T Wq) p.
// k, v never materialized: s_ij = q'_i . p_j ; out = Wv (sum e p)/sum e.
// sincosf shares one range-reduction for the /25 pair.
// ---------------------------------------------------------------------------
__global__ __launch_bounds__(64)
void prep_kernel(const int* __restrict__ x,
                 const float* __restrict__ emb,
                 const float* __restrict__ Wk,
                 const float* __restrict__ Wq) {
    int t = blockIdx.x * blockDim.x + threadIdx.x;
    if (t >= T_LEN) return;

    int xi = x[t];
    xi = min(max(xi, 0), VOCAB - 1);

    // positional encoding — mirror reference fp32 op order: (6.28f*t)/c
    float a = 6.28f * (float)t;
    float s25, c25;
    sincosf(a / 25.0f, &s25, &c25);
    float p0 = emb[xi * 3 + 0] + c25;
    float p1 = emb[xi * 3 + 1] + s25;
    float p2 = emb[xi * 3 + 2] + sinf(a / 5.0f);

    const float QSCALE = 0.8329465708f;  // log2(e) / sqrt(3)

    // q' = QSCALE * (Wk^T Wq) p
    float q0 = 0.f, q1 = 0.f, q2 = 0.f;
    #pragma unroll
    for (int aa = 0; aa < 3; ++aa) {
        float qq = fmaf(Wq[aa * 3 + 0], p0,
                   fmaf(Wq[aa * 3 + 1], p1, Wq[aa * 3 + 2] * p2)); // (Wq p)_a
        q0 = fmaf(Wk[aa * 3 + 0], qq, q0);
        q1 = fmaf(Wk[aa * 3 + 1], qq, q1);
        q2 = fmaf(Wk[aa * 3 + 2], qq, q2);
    }
    g_qp[t] = make_float4(q0 * QSCALE, q1 * QSCALE, q2 * QSCALE, 0.0f);
    g_p[t]  = make_float4(p0, p1, p2, 1.0f);
}

// ---------------------------------------------------------------------------
// Kernel 2: fused attention + last-arrival tail reduce.
// grid = (16, 37) = 592 CTAs x 128 thr = 4 CTAs/SM, one wave.
// The 37th CTA to finish each qblock does the fixed-order reduce for its 512
// queries (deterministic: summation order is fixed, executor identity isn't).
// Counter is monotonic (never reset) -> graph-replay safe via mod-37 test.
// ---------------------------------------------------------------------------
__global__ __launch_bounds__(NTHREADS)
void attn_kernel(const float* __restrict__ Wv, float* __restrict__ out) {
    __shared__ float4 sp[KMAX];
    __shared__ unsigned s_old;

    const int tid  = threadIdx.x;
    const int c    = blockIdx.y;
    const int kbeg = (c * T_LEN) / NCHUNK;
    const int kend = ((c + 1) * T_LEN) / NCHUNK;
    const int klen = kend - kbeg;

    for (int i = tid; i < klen; i += NTHREADS)
        sp[i] = g_p[kbeg + i];
    __syncthreads();

    const int qbase = blockIdx.x * QBLK + tid;
    float3 q[QPT];
    #pragma unroll
    for (int u = 0; u < QPT; ++u) {
        float4 t4 = g_qp[qbase + u * NTHREADS];
        q[u] = make_float3(t4.x, t4.y, t4.z);
    }

    float den[QPT], a0[QPT], a1[QPT], a2[QPT];
    #pragma unroll
    for (int u = 0; u < QPT; ++u) { den[u] = a0[u] = a1[u] = a2[u] = 0.0f; }

    #pragma unroll 4
    for (int j = 0; j < klen; ++j) {
        float4 p = sp[j];
        #pragma unroll
        for (int u = 0; u < QPT; ++u) {
            float s = fmaf(q[u].x, p.x, fmaf(q[u].y, p.y, q[u].z * p.z));
            float e = ex2f(s);
            den[u] += e;
            a0[u]  = fmaf(e, p.x, a0[u]);
            a1[u]  = fmaf(e, p.y, a1[u]);
            a2[u]  = fmaf(e, p.z, a2[u]);
        }
    }

    #pragma unroll
    for (int u = 0; u < QPT; ++u)
        g_part[c * T_LEN + qbase + u * NTHREADS] =
            make_float4(a0[u], a1[u], a2[u], den[u]);

    // ---- last-arrival tail reduce (no spinning) ----
    __threadfence();                 // partials visible before counter bump
    __syncthreads();                 // all warps' stores issued
    if (tid == 0)
        s_old = atomicAdd(&g_cnt[blockIdx.x], 1u);
    __syncthreads();

    if (s_old % NCHUNK == NCHUNK - 1) {
        // this CTA saw all 36 other arrivals -> their fenced writes are visible
        #pragma unroll
        for (int u = 0; u < QPT; ++u) {
            int qq = blockIdx.x * QBLK + tid + u * NTHREADS;
            float r0 = 0.f, r1 = 0.f, r2 = 0.f, rd = 0.f;
            #pragma unroll 4
            for (int s = 0; s < NCHUNK; ++s) {          // fixed order: deterministic
                float4 p = g_part[s * T_LEN + qq];
                r0 += p.x; r1 += p.y; r2 += p.z; rd += p.w;
            }
            float inv = 1.0f / rd;
            out[qq * 3 + 0] = fmaf(Wv[0], r0, fmaf(Wv[1], r1, Wv[2] * r2)) * inv;
            out[qq * 3 + 1] = fmaf(Wv[3], r0, fmaf(Wv[4], r1, Wv[5] * r2)) * inv;
            out[qq * 3 + 2] = fmaf(Wv[6], r0, fmaf(Wv[7], r1, Wv[8] * r2)) * inv;
        }
    }
}

extern "C" void kernel_launch(void* const* d_in, const int* in_sizes, int n_in,
                              void* d_out, int out_size) {
    const int*   x   = (const int*)  d_in[0];
    const float* emb = (const float*)d_in[1];
    const float* Wk  = (const float*)d_in[2];
    const float* Wq  = (const float*)d_in[3];
    const float* Wv  = (const float*)d_in[4];
    float* out = (float*)d_out;

    prep_kernel<<<T_LEN / 64, 64>>>(x, emb, Wk, Wq);
    attn_kernel<<<dim3(NQBLK, NCHUNK), NTHREADS>>>(Wv, out);
}

// round 10
// speedup vs baseline: 1.2924x; 1.2924x over previous
#include <cuda_runtime.h>
#include <cuda_bf16.h>
#include <math.h>

#define T_LEN    8192
#define VOCAB    50257
#define NCHUNK   37               // 16 qblocks x 37 chunks = 592 CTAs = exactly 4/SM
#define NQBLK    16
#define QBLK     512              // queries per CTA
#define NTHREADS 128
#define QPT      4
#define KMAX     222              // ceil(8192/37)

// scratch (device globals; no allocation allowed)
__device__ float4 g_qp[T_LEN];                // q' = QSCALE * (Wk^T Wq) p
__device__ float4 g_p[T_LEN];                 // p with w=1.0f
__device__ float4 g_part[NCHUNK * T_LEN];     // per-chunk partial (sum e*p, sum e)

__device__ __forceinline__ float ex2f(float x) {
    float r; asm("ex2.approx.f32 %0, %1;" : "=f"(r) : "f"(x)); return r;
}

// FMA-pipe exp2: exact for the integer part (bit-trick), deg-5 Taylor on the
// fraction f in [-0.5, 0.5] (max rel err ~2e-6). Zero MUFU usage.
__device__ __forceinline__ float exp2_poly(float s) {
    const float MAGIC = 12582912.0f;           // 2^23 * 1.5
    float t  = s + MAGIC;                      // round-to-nearest into mantissa
    float n  = t - MAGIC;
    float f  = s - n;                          // f in [-0.5, 0.5]
    int   ni = __float_as_int(t) - 0x4B400000; // integer n (exact)
    float p;
    p = fmaf(f, 0.0013333558f, 0.0096181291f);
    p = fmaf(f, p, 0.0555041087f);
    p = fmaf(f, p, 0.2402265070f);
    p = fmaf(f, p, 0.6931471806f);
    p = fmaf(f, p, 1.0f);
    return __int_as_float(__float_as_int(p) + (ni << 23));  // p * 2^n
}

// ---------------------------------------------------------------------------
// Kernel 1: gather + posenc; emit p and q' = QSCALE*(Wk^T Wq) p.
// ---------------------------------------------------------------------------
__global__ __launch_bounds__(64)
void prep_kernel(const int* __restrict__ x,
                 const float* __restrict__ emb,
                 const float* __restrict__ Wk,
                 const float* __restrict__ Wq) {
    int t = blockIdx.x * blockDim.x + threadIdx.x;
    if (t >= T_LEN) return;

    int xi = x[t];
    xi = min(max(xi, 0), VOCAB - 1);

    // positional encoding — mirror reference fp32 op order: (6.28f*t)/c
    float a = 6.28f * (float)t;
    float s25, c25;
    sincosf(a / 25.0f, &s25, &c25);
    float p0 = emb[xi * 3 + 0] + c25;
    float p1 = emb[xi * 3 + 1] + s25;
    float p2 = emb[xi * 3 + 2] + sinf(a / 5.0f);

    const float QSCALE = 0.8329465708f;  // log2(e) / sqrt(3)

    // q' = QSCALE * (Wk^T Wq) p
    float q0 = 0.f, q1 = 0.f, q2 = 0.f;
    #pragma unroll
    for (int aa = 0; aa < 3; ++aa) {
        float qq = fmaf(Wq[aa * 3 + 0], p0,
                   fmaf(Wq[aa * 3 + 1], p1, Wq[aa * 3 + 2] * p2)); // (Wq p)_a
        q0 = fmaf(Wk[aa * 3 + 0], qq, q0);
        q1 = fmaf(Wk[aa * 3 + 1], qq, q1);
        q2 = fmaf(Wk[aa * 3 + 2], qq, q2);
    }
    g_qp[t] = make_float4(q0 * QSCALE, q1 * QSCALE, q2 * QSCALE, 0.0f);
    g_p[t]  = make_float4(p0, p1, p2, 1.0f);
}

// ---------------------------------------------------------------------------
// Kernel 2: fused attention, no-max softmax. Mixed exp pipes: queries 0,1 use
// MUFU ex2; queries 2,3 use the FMA-pipe poly. This cuts MUFU demand 2x to
// break the issue<->MUFU serialization seen in profiles.
// grid = (16, 37) = 592 CTAs x 128 thr = 4 CTAs/SM, one wave.
// ---------------------------------------------------------------------------
__global__ __launch_bounds__(NTHREADS)
void attn_kernel() {
    __shared__ float4 sp[KMAX];

    const int tid  = threadIdx.x;
    const int c    = blockIdx.y;
    const int kbeg = (c * T_LEN) / NCHUNK;
    const int kend = ((c + 1) * T_LEN) / NCHUNK;
    const int klen = kend - kbeg;

    for (int i = tid; i < klen; i += NTHREADS)
        sp[i] = g_p[kbeg + i];
    __syncthreads();

    const int qbase = blockIdx.x * QBLK + tid;
    float3 q[QPT];
    #pragma unroll
    for (int u = 0; u < QPT; ++u) {
        float4 t4 = g_qp[qbase + u * NTHREADS];
        q[u] = make_float3(t4.x, t4.y, t4.z);
    }

    float den[QPT], a0[QPT], a1[QPT], a2[QPT];
    #pragma unroll
    for (int u = 0; u < QPT; ++u) { den[u] = a0[u] = a1[u] = a2[u] = 0.0f; }

    #pragma unroll 4
    for (int j = 0; j < klen; ++j) {
        float4 p = sp[j];
        #pragma unroll
        for (int u = 0; u < QPT; ++u) {
            float s = fmaf(q[u].x, p.x, fmaf(q[u].y, p.y, q[u].z * p.z));
            float e = (u < 2) ? ex2f(s) : exp2_poly(s);
            den[u] += e;
            a0[u]  = fmaf(e, p.x, a0[u]);
            a1[u]  = fmaf(e, p.y, a1[u]);
            a2[u]  = fmaf(e, p.z, a2[u]);
        }
    }

    #pragma unroll
    for (int u = 0; u < QPT; ++u)
        g_part[c * T_LEN + qbase + u * NTHREADS] =
            make_float4(a0[u], a1[u], a2[u], den[u]);
}

// ---------------------------------------------------------------------------
// Kernel 3: deterministic fixed-order reduce over NCHUNK partials, then
// apply Wv once per query and divide.
// ---------------------------------------------------------------------------
__global__ __launch_bounds__(256)
void reduce_kernel(const float* __restrict__ Wv, float* __restrict__ out) {
    int t = blockIdx.x * blockDim.x + threadIdx.x;
    if (t >= T_LEN) return;

    float r0 = 0.f, r1 = 0.f, r2 = 0.f, rd = 0.f;
    #pragma unroll
    for (int s = 0; s < NCHUNK; ++s) {
        float4 p = g_part[s * T_LEN + t];
        r0 += p.x; r1 += p.y; r2 += p.z; rd += p.w;
    }
    float inv = 1.0f / rd;
    out[t * 3 + 0] = fmaf(Wv[0], r0, fmaf(Wv[1], r1, Wv[2] * r2)) * inv;
    out[t * 3 + 1] = fmaf(Wv[3], r0, fmaf(Wv[4], r1, Wv[5] * r2)) * inv;
    out[t * 3 + 2] = fmaf(Wv[6], r0, fmaf(Wv[7], r1, Wv[8] * r2)) * inv;
}

extern "C" void kernel_launch(void* const* d_in, const int* in_sizes, int n_in,
                              void* d_out, int out_size) {
    const int*   x   = (const int*)  d_in[0];
    const float* emb = (const float*)d_in[1];
    const float* Wk  = (const float*)d_in[2];
    const float* Wq  = (const float*)d_in[3];
    const float* Wv  = (const float*)d_in[4];
    float* out = (float*)d_out;

    prep_kernel<<<T_LEN / 64, 64>>>(x, emb, Wk, Wq);
    attn_kernel<<<dim3(NQBLK, NCHUNK), NTHREADS>>>();
    reduce_kernel<<<T_LEN / 256, 256>>>(Wv, out);
}

// round 11
// speedup vs baseline: 1.3539x; 1.0476x over previous
#include <cuda_runtime.h>
#include <cuda_bf16.h>
#include <math.h>

#define T_LEN    8192
#define VOCAB    50257
#define NCHUNK   9                // key chunks
#define CHUNK    912              // keys per chunk (mult of 8); 9*912 = 8208 >= 8192
#define NQTILE   64               // q CTAs; each CTA = 128 queries (4 warps x 32)
#define NTHREADS 128

// scratch (device globals; no allocation allowed)
__device__ float4 g_qp[T_LEN];                 // q' = QSCALE*(Wk^T Wq) p
__device__ float4 g_p4[T_LEN];                 // (px,py,pz,1) fp32
__device__ float4 g_p4h[T_LEN];                // tf32 hi of p4
__device__ float4 g_p4l[T_LEN];                // tf32 lo of p4
__device__ float  g_part[NCHUNK][T_LEN][4];    // per-chunk (Se*px, Se*py, Se*pz, Se)

__device__ __forceinline__ float ex2f(float x) {
    float r; asm("ex2.approx.f32 %0, %1;" : "=f"(r) : "f"(x)); return r;
}
__device__ __forceinline__ unsigned f2tf32(float x) {
    unsigned r; asm("cvt.rna.tf32.f32 %0, %1;" : "=r"(r) : "f"(x)); return r;
}
// exp2 then round to tf32 (bits in a b32 reg, ready as MMA A-operand)
__device__ __forceinline__ unsigned e2t(float s) { return f2tf32(ex2f(s)); }

__device__ __forceinline__ float dot3(float3 q, float4 p) {
    return fmaf(q.x, p.x, fmaf(q.y, p.y, q.z * p.z));
}

// mma.sync m16n8k8 tf32: D = A*B + C (C==D registers)
__device__ __forceinline__ void mma_tf32(float c[4],
                                         unsigned a0, unsigned a1, unsigned a2, unsigned a3,
                                         unsigned b0, unsigned b1) {
    asm volatile(
        "mma.sync.aligned.m16n8k8.row.col.f32.tf32.tf32.f32 "
        "{%0,%1,%2,%3}, {%4,%5,%6,%7}, {%8,%9}, {%0,%1,%2,%3};"
        : "+f"(c[0]), "+f"(c[1]), "+f"(c[2]), "+f"(c[3])
        : "r"(a0), "r"(a1), "r"(a2), "r"(a3), "r"(b0), "r"(b1));
}

// ---------------------------------------------------------------------------
// Kernel 1: gather + posenc; emit q' (pre-scaled), p4 fp32, and tf32 hi/lo.
// ---------------------------------------------------------------------------
__global__ __launch_bounds__(64)
void prep_kernel(const int* __restrict__ x,
                 const float* __restrict__ emb,
                 const float* __restrict__ Wk,
                 const float* __restrict__ Wq) {
    int t = blockIdx.x * blockDim.x + threadIdx.x;
    if (t >= T_LEN) return;

    int xi = x[t];
    xi = min(max(xi, 0), VOCAB - 1);

    // positional encoding — mirror reference fp32 op order: (6.28f*t)/c
    float a = 6.28f * (float)t;
    float s25, c25;
    sincosf(a / 25.0f, &s25, &c25);
    float p0 = emb[xi * 3 + 0] + c25;
    float p1 = emb[xi * 3 + 1] + s25;
    float p2 = emb[xi * 3 + 2] + sinf(a / 5.0f);

    const float QSCALE = 0.8329465708f;  // log2(e)/sqrt(3)

    // q' = QSCALE * (Wk^T Wq) p
    float q0 = 0.f, q1 = 0.f, q2 = 0.f;
    #pragma unroll
    for (int aa = 0; aa < 3; ++aa) {
        float qq = fmaf(Wq[aa * 3 + 0], p0,
                   fmaf(Wq[aa * 3 + 1], p1, Wq[aa * 3 + 2] * p2));
        q0 = fmaf(Wk[aa * 3 + 0], qq, q0);
        q1 = fmaf(Wk[aa * 3 + 1], qq, q1);
        q2 = fmaf(Wk[aa * 3 + 2], qq, q2);
    }
    g_qp[t] = make_float4(q0 * QSCALE, q1 * QSCALE, q2 * QSCALE, 0.0f);

    float4 p4 = make_float4(p0, p1, p2, 1.0f);
    g_p4[t] = p4;

    float h0 = __uint_as_float(f2tf32(p4.x));
    float h1 = __uint_as_float(f2tf32(p4.y));
    float h2 = __uint_as_float(f2tf32(p4.z));
    float h3 = 1.0f;                                  // exactly representable
    g_p4h[t] = make_float4(h0, h1, h2, h3);
    g_p4l[t] = make_float4(__uint_as_float(f2tf32(p4.x - h0)),
                           __uint_as_float(f2tf32(p4.y - h1)),
                           __uint_as_float(f2tf32(p4.z - h2)),
                           0.0f);
}

// ---------------------------------------------------------------------------
// Kernel 2: attention with tensor-core accumulation.
// grid = (64, 9) = 576 CTAs x 128 thr. Warp handles 32 queries (2 m16n8 tiles),
// loops over its chunk in 8-key steps. Scores: scalar fp32 dot + ex2, rounded
// to tf32 directly into the A-fragment slots. Accumulation (Σe·[p,1]) done by
// mma.sync with B = tf32(hi)+tf32(lo) split (2 MMAs) — exact in p.
// Pad keys (>=8192): p4 == 0 -> B columns zero -> contribute nothing.
// ---------------------------------------------------------------------------
__global__ __launch_bounds__(NTHREADS)
void attn_kernel() {
    __shared__ float4 sp [CHUNK];   // fp32 p4 (for dots)
    __shared__ float4 sph[CHUNK];   // tf32 hi bits (as floats)
    __shared__ float4 spl[CHUNK];   // tf32 lo bits

    const int tid  = threadIdx.x;
    const int warp = tid >> 5;
    const int lane = tid & 31;
    const int g    = lane >> 2;     // groupID  (0..7)
    const int tg   = lane & 3;      // threadID in group (0..3)
    const int kbeg = blockIdx.y * CHUNK;

    for (int i = tid; i < CHUNK; i += NTHREADS) {
        int idx = kbeg + i;
        if (idx < T_LEN) {
            sp[i] = g_p4[idx]; sph[i] = g_p4h[idx]; spl[i] = g_p4l[idx];
        } else {
            float4 z = make_float4(0.f, 0.f, 0.f, 0.f);
            sp[i] = z; sph[i] = z; spl[i] = z;
        }
    }
    __syncthreads();

    // warp's 32 queries: rows qbase+0..15 (tile0), qbase+16..31 (tile1)
    const int qbase = blockIdx.x * 128 + warp * 32;
    float3 q0, q1, q2, q3;
    { float4 t4 = g_qp[qbase + g     ]; q0 = make_float3(t4.x, t4.y, t4.z); }
    { float4 t4 = g_qp[qbase + g +  8]; q1 = make_float3(t4.x, t4.y, t4.z); }
    { float4 t4 = g_qp[qbase + g + 16]; q2 = make_float3(t4.x, t4.y, t4.z); }
    { float4 t4 = g_qp[qbase + g + 24]; q3 = make_float3(t4.x, t4.y, t4.z); }

    float c0[4] = {0.f, 0.f, 0.f, 0.f};   // tile0 accumulators
    float c1[4] = {0.f, 0.f, 0.f, 0.f};   // tile1 accumulators

    const float* sphf = (const float*)sph;
    const float* splf = (const float*)spl;

    #pragma unroll 2
    for (int j = 0; j < CHUNK; j += 8) {
        float4 pa = sp[j + tg];         // key ka = j+tg     (A cols 0..3)
        float4 pb = sp[j + tg + 4];     // key kb = j+tg+4   (A cols 4..7)

        // A fragments (e as tf32): a0:(row g, ka) a1:(g+8, ka) a2:(g, kb) a3:(g+8, kb)
        unsigned a0 = e2t(dot3(q0, pa));
        unsigned a1 = e2t(dot3(q1, pa));
        unsigned a2 = e2t(dot3(q0, pb));
        unsigned a3 = e2t(dot3(q1, pb));
        unsigned a4 = e2t(dot3(q2, pa));
        unsigned a5 = e2t(dot3(q3, pa));
        unsigned a6 = e2t(dot3(q2, pb));
        unsigned a7 = e2t(dot3(q3, pb));

        // B fragments: b0:(k=tg, n=g) b1:(k=tg+4, n=g); cols n>=4 are zero
        unsigned bh0 = 0u, bh1 = 0u, bl0 = 0u, bl1 = 0u;
        if (g < 4) {
            bh0 = __float_as_uint(sphf[(j + tg) * 4 + g]);
            bh1 = __float_as_uint(sphf[(j + tg + 4) * 4 + g]);
            bl0 = __float_as_uint(splf[(j + tg) * 4 + g]);
            bl1 = __float_as_uint(splf[(j + tg + 4) * 4 + g]);
        }

        mma_tf32(c0, a0, a1, a2, a3, bh0, bh1);
        mma_tf32(c0, a0, a1, a2, a3, bl0, bl1);
        mma_tf32(c1, a4, a5, a6, a7, bh0, bh1);
        mma_tf32(c1, a4, a5, a6, a7, bl0, bl1);
    }

    // C layout: c[0]:(row g, col 2tg) c[1]:(g, 2tg+1) c[2]:(g+8, 2tg) c[3]:(g+8, 2tg+1)
    // real cols 0..3 = (Se*px, Se*py, Se*pz, Se) -> threads tg<2 write float2 each
    if (tg < 2) {
        const int cc = blockIdx.y;
        float2* o;
        o = (float2*)&g_part[cc][qbase + g     ][2 * tg]; *o = make_float2(c0[0], c0[1]);
        o = (float2*)&g_part[cc][qbase + g +  8][2 * tg]; *o = make_float2(c0[2], c0[3]);
        o = (float2*)&g_part[cc][qbase + g + 16][2 * tg]; *o = make_float2(c1[0], c1[1]);
        o = (float2*)&g_part[cc][qbase + g + 24][2 * tg]; *o = make_float2(c1[2], c1[3]);
    }
}

// ---------------------------------------------------------------------------
// Kernel 3: deterministic fixed-order reduce over NCHUNK partials, then Wv
// and divide.
// ---------------------------------------------------------------------------
__global__ __launch_bounds__(256)
void reduce_kernel(const float* __restrict__ Wv, float* __restrict__ out) {
    int t = blockIdx.x * blockDim.x + threadIdx.x;
    if (t >= T_LEN) return;

    float r0 = 0.f, r1 = 0.f, r2 = 0.f, rd = 0.f;
    #pragma unroll
    for (int s = 0; s < NCHUNK; ++s) {
        const float* p = g_part[s][t];
        r0 += p[0]; r1 += p[1]; r2 += p[2]; rd += p[3];
    }
    float inv = 1.0f / rd;
    out[t * 3 + 0] = fmaf(Wv[0], r0, fmaf(Wv[1], r1, Wv[2] * r2)) * inv;
    out[t * 3 + 1] = fmaf(Wv[3], r0, fmaf(Wv[4], r1, Wv[5] * r2)) * inv;
    out[t * 3 + 2] = fmaf(Wv[6], r0, fmaf(Wv[7], r1, Wv[8] * r2)) * inv;
}

extern "C" void kernel_launch(void* const* d_in, const int* in_sizes, int n_in,
                              void* d_out, int out_size) {
    const int*   x   = (const int*)  d_in[0];
    const float* emb = (const float*)d_in[1];
    const float* Wk  = (const float*)d_in[2];
    const float* Wq  = (const float*)d_in[3];
    const float* Wv  = (const float*)d_in[4];
    float* out = (float*)d_out;

    prep_kernel<<<T_LEN / 64, 64>>>(x, emb, Wk, Wq);
    attn_kernel<<<dim3(NQTILE, NCHUNK), NTHREADS>>>();
    reduce_kernel<<<T_LEN / 256, 256>>>(Wv, out);
}